// round 1
// baseline (speedup 1.0000x reference)
#include <cuda_runtime.h>
#include <math.h>

// ---------------- problem constants ----------------
#define BB 8
#define TT 1024
#define CIN 55
#define DD 512
#define LL 3
#define SEQW 10
#define TRR 512          // masked count
#define TU 512           // unmasked count (T - TR)

// ---------------- device scratch ----------------
__device__ float g_pe[TT * DD];
__device__ float g_ex[BB * TT * DD];
__device__ float g_xe[BB * TU * DD];
__device__ float g_q [BB * TT * DD];
__device__ float g_k [BB * TT * DD];
__device__ float g_v [BB * TT * DD];
__device__ float g_att[BB * TU * TU];     // encoder attention scratch
__device__ float g_t1[BB * TT * DD];
__device__ float g_t2[BB * TT * DD];
__device__ float g_tok[BB * TT * DD];
__device__ float g_score[BB * TT];
__device__ int   g_flag[BB * TT];
__device__ int   g_upos[BB * TT];
__device__ int   g_ulist[BB * TU];

// ---------------- PE ----------------
__global__ void pe_kernel() {
    int t = blockIdx.x;
    int i = threadIdx.x;                 // 0..255
    float divv = expf((float)(2 * i) * (-9.210340371976184f / (float)DD));
    float ang = (float)t * divv;
    g_pe[t * DD + 2 * i]     = sinf(ang);
    g_pe[t * DD + 2 * i + 1] = cosf(ang);
}

// ---------------- embedding: circular conv1d + PE ----------------
__global__ void embed_kernel(const float* __restrict__ x, const float* __restrict__ cw,
                             float* __restrict__ ex) {
    int t = blockIdx.x, b = blockIdx.y;
    __shared__ float sw[CIN * 3];
    int tid = threadIdx.x;               // 128 threads
    for (int i = tid; i < CIN * 3; i += 128) {
        int c = i / 3, k = i % 3;
        int tt = t + k - 1;
        if (tt < 0) tt += TT;
        if (tt >= TT) tt -= TT;
        sw[i] = x[((long long)b * TT + tt) * CIN + c];
    }
    __syncthreads();
#pragma unroll
    for (int p = 0; p < 4; p++) {
        int d = tid + p * 128;
        const float* w = cw + (long long)d * (CIN * 3);
        float acc = 0.f;
#pragma unroll 15
        for (int i = 0; i < CIN * 3; i++) acc = fmaf(sw[i], w[i], acc);
        ex[((long long)b * TT + t) * DD + d] = acc + g_pe[t * DD + d];
    }
}

// ---------------- windowed mean/var score ----------------
__global__ void score_kernel(const float* __restrict__ ex, float* __restrict__ score) {
    int t = blockIdx.x, b = blockIdx.y;
    int lo = t - (SEQW - 1); if (lo < 0) lo = 0;
    float inv = 1.f / (float)(t + 1 - lo);
    int tid = threadIdx.x;               // 256
    float vs = 0.f, ms = 0.f;
#pragma unroll
    for (int p = 0; p < 2; p++) {
        int d = tid + p * 256;
        float s1 = 0.f, s2 = 0.f;
        for (int w = lo; w <= t; w++) {
            float v = ex[((long long)b * TT + w) * DD + d];
            s1 += v; s2 += v * v;
        }
        float m = s1 * inv, m2 = s2 * inv;
        vs += m2 - m * m;
        ms += m;
    }
    __shared__ float rv[256], rm[256];
    rv[tid] = vs; rm[tid] = ms; __syncthreads();
    for (int s = 128; s > 0; s >>= 1) {
        if (tid < s) { rv[tid] += rv[tid + s]; rm[tid] += rm[tid + s]; }
        __syncthreads();
    }
    if (tid == 0) score[b * TT + t] = rv[0] / rm[0];
}

// ---------------- selection: rank with top_k tie-break ----------------
__global__ void select_kernel() {
    int b = blockIdx.x;
    int t = threadIdx.x;                 // 1024 threads
    __shared__ float ss[TT];
    __shared__ int   sf[TT];
    float myv = g_score[b * TT + t];
    ss[t] = myv;
    __syncthreads();
    int rank = 0;
    for (int i = 0; i < TT; i++) {
        float o = ss[i];
        rank += (o > myv) || (o == myv && i < t);
    }
    int masked = (rank < TRR) ? 1 : 0;
    sf[t] = masked;
    __syncthreads();
    int ucnt = 0;
    for (int i = 0; i < t; i++) ucnt += (sf[i] == 0);
    g_flag[b * TT + t] = masked;
    if (!masked) {
        g_upos[b * TT + t] = ucnt;
        g_ulist[b * TU + ucnt] = t;
    } else {
        g_upos[b * TT + t] = -1;
    }
}

// ---------------- gather unmasked tokens ----------------
__global__ void gather_kernel(const float* __restrict__ ex, float* __restrict__ xe) {
    int p = blockIdx.x, b = blockIdx.y;
    int t = g_ulist[b * TU + p];
    const float* src = ex + ((long long)b * TT + t) * DD;
    float* dst = xe + ((long long)b * TU + p) * DD;
    for (int d = threadIdx.x; d < DD; d += 256) dst[d] = src[d];
}

// ---------------- build decoder tokens ----------------
__global__ void tokens_kernel(const float* __restrict__ ux, const float* __restrict__ mtk,
                              float* __restrict__ tok) {
    int t = blockIdx.x, b = blockIdx.y;
    float* dst = tok + ((long long)b * TT + t) * DD;
    if (g_flag[b * TT + t]) {
        for (int d = threadIdx.x; d < DD; d += 256)
            dst[d] = mtk[d] + g_pe[t * DD + d];
    } else {
        int p = g_upos[b * TT + t];
        const float* src = ux + ((long long)b * TU + p) * DD;
        for (int d = threadIdx.x; d < DD; d += 256) dst[d] = src[d];
    }
}

// ---------------- generic tiled GEMM ----------------
// C[b] = epi(alpha * A[b] @ op(B[b]) + bias + resid[b])
// op(B) = B ([K,N]) if !transB else B^T with B stored [N,K]
__global__ __launch_bounds__(256)
void gemm_kernel(const float* __restrict__ A, const float* __restrict__ B,
                 const float* __restrict__ bias, const float* __restrict__ resid,
                 float* __restrict__ C,
                 int M, int N, int K,
                 long long sA, long long sB, long long sC,
                 float alpha, int transB, int epi) {
    int bz = blockIdx.z;
    A += (long long)bz * sA;
    B += (long long)bz * sB;
    C += (long long)bz * sC;
    const float* R = resid ? resid + (long long)bz * sC : nullptr;

    __shared__ float As[16][65];
    __shared__ float Bs[16][65];

    int tx = threadIdx.x, ty = threadIdx.y;     // 16x16
    int tid = ty * 16 + tx;
    int m0 = blockIdx.y * 64;
    int n0 = blockIdx.x * 64;

    float acc[4][4] = {};
    for (int k0 = 0; k0 < K; k0 += 16) {
        {
            int kk = tid & 15;
            int mb = tid >> 4;
#pragma unroll
            for (int p = 0; p < 4; p++) {
                int m = mb + p * 16;
                float v = 0.f;
                if (m0 + m < M && k0 + kk < K) v = A[(long long)(m0 + m) * K + k0 + kk];
                As[kk][m] = v;
            }
        }
        if (!transB) {
            int n = tid & 63;
            int kb = tid >> 6;
#pragma unroll
            for (int p = 0; p < 4; p++) {
                int kk = kb + p * 4;
                float v = 0.f;
                if (k0 + kk < K && n0 + n < N) v = B[(long long)(k0 + kk) * N + n0 + n];
                Bs[kk][n] = v;
            }
        } else {
            int kk = tid & 15;
            int nb = tid >> 4;
#pragma unroll
            for (int p = 0; p < 4; p++) {
                int n = nb + p * 16;
                float v = 0.f;
                if (n0 + n < N && k0 + kk < K) v = B[(long long)(n0 + n) * K + k0 + kk];
                Bs[kk][n] = v;
            }
        }
        __syncthreads();
#pragma unroll
        for (int kk = 0; kk < 16; kk++) {
            float a[4], bq[4];
#pragma unroll
            for (int i = 0; i < 4; i++) a[i] = As[kk][ty * 4 + i];
#pragma unroll
            for (int j = 0; j < 4; j++) bq[j] = Bs[kk][tx * 4 + j];
#pragma unroll
            for (int i = 0; i < 4; i++)
#pragma unroll
                for (int j = 0; j < 4; j++)
                    acc[i][j] = fmaf(a[i], bq[j], acc[i][j]);
        }
        __syncthreads();
    }
#pragma unroll
    for (int i = 0; i < 4; i++) {
        int m = m0 + ty * 4 + i;
        if (m >= M) continue;
#pragma unroll
        for (int j = 0; j < 4; j++) {
            int n = n0 + tx * 4 + j;
            if (n >= N) continue;
            float v = acc[i][j] * alpha;
            if (bias) v += bias[n];
            if (R) v += R[(long long)m * N + n];
            if (epi == 1) v = 0.5f * v * (1.f + erff(v * 0.7071067811865475f));   // exact gelu
            else if (epi == 2) v = 1.f / (1.f + __expf(-v));                     // sigmoid
            C[(long long)m * N + n] = v;
        }
    }
}

// ---------------- softmax over rows ----------------
__global__ void softmax_kernel(float* __restrict__ S, int Nc) {
    long long row = blockIdx.x;
    float* p = S + row * Nc;
    __shared__ float red[256];
    int tid = threadIdx.x;
    float mx = -1e30f;
    for (int i = tid; i < Nc; i += 256) mx = fmaxf(mx, p[i]);
    red[tid] = mx; __syncthreads();
    for (int s = 128; s > 0; s >>= 1) { if (tid < s) red[tid] = fmaxf(red[tid], red[tid + s]); __syncthreads(); }
    mx = red[0]; __syncthreads();
    float sum = 0.f;
    for (int i = tid; i < Nc; i += 256) { float e = __expf(p[i] - mx); p[i] = e; sum += e; }
    red[tid] = sum; __syncthreads();
    for (int s = 128; s > 0; s >>= 1) { if (tid < s) red[tid] += red[tid + s]; __syncthreads(); }
    float inv = 1.f / red[0];
    for (int i = tid; i < Nc; i += 256) p[i] *= inv;
}

// ---------------- layer norm (row length 512) ----------------
__global__ void ln_kernel(const float* __restrict__ X, const float* __restrict__ g,
                          const float* __restrict__ b, float* __restrict__ Y) {
    long long row = blockIdx.x;
    const float* x = X + row * DD;
    float* y = Y + row * DD;
    __shared__ float red[256];
    int tid = threadIdx.x;
    float v0 = x[tid], v1 = x[tid + 256];
    red[tid] = v0 + v1; __syncthreads();
    for (int s = 128; s > 0; s >>= 1) { if (tid < s) red[tid] += red[tid + s]; __syncthreads(); }
    float mu = red[0] * (1.f / (float)DD); __syncthreads();
    float d0 = v0 - mu, d1 = v1 - mu;
    red[tid] = d0 * d0 + d1 * d1; __syncthreads();
    for (int s = 128; s > 0; s >>= 1) { if (tid < s) red[tid] += red[tid + s]; __syncthreads(); }
    float inv = rsqrtf(red[0] * (1.f / (float)DD) + 1e-5f);
    y[tid]       = d0 * inv * g[tid] + b[tid];
    y[tid + 256] = d1 * inv * g[tid + 256] + b[tid + 256];
}

// ---------------- elementwise add ----------------
__global__ void add_kernel(float* __restrict__ A, const float* __restrict__ B, long long n) {
    long long i = (long long)blockIdx.x * blockDim.x + threadIdx.x;
    if (i < n) A[i] += B[i];
}

// ---------------- host orchestration ----------------
extern "C" void kernel_launch(void* const* d_in, const int* in_sizes, int n_in,
                              void* d_out, int out_size) {
    // scratch pointers
    float *pe, *ex, *xe, *q, *k, *v, *att, *t1, *t2, *tok, *score;
    cudaGetSymbolAddress((void**)&pe,  g_pe);
    cudaGetSymbolAddress((void**)&ex,  g_ex);
    cudaGetSymbolAddress((void**)&xe,  g_xe);
    cudaGetSymbolAddress((void**)&q,   g_q);
    cudaGetSymbolAddress((void**)&k,   g_k);
    cudaGetSymbolAddress((void**)&v,   g_v);
    cudaGetSymbolAddress((void**)&att, g_att);
    cudaGetSymbolAddress((void**)&t1,  g_t1);
    cudaGetSymbolAddress((void**)&t2,  g_t2);
    cudaGetSymbolAddress((void**)&tok, g_tok);
    cudaGetSymbolAddress((void**)&score, g_score);

    const float* in[31];
    for (int i = 0; i < 31 && i < n_in; i++) in[i] = (const float*)d_in[i];

    const float *x = in[0], *conv_w = in[1], *mask_token = in[2];
    const float *pro_w1, *pro_b1, *pro_w2, *pro_b2;
    const float *eW[4], *eBi[4], *eg, *ebb, *eng, *enb;   // enc: Wq,Wk,Wv,Wo / bq,bk,bv,bo
    const float *dW[4], *dBi[4], *dg, *dbb, *dng, *dnb;

    bool sig = (in_sizes[3] == LL * DD * DD);  // 786432 -> reference-signature order
    if (sig) {
        eW[0]=in[3];  eBi[0]=in[4];  eW[1]=in[5];  eBi[1]=in[6];
        eW[2]=in[7];  eBi[2]=in[8];  eW[3]=in[9];  eBi[3]=in[10];
        eg=in[11]; ebb=in[12]; eng=in[13]; enb=in[14];
        dW[0]=in[15]; dBi[0]=in[16]; dW[1]=in[17]; dBi[1]=in[18];
        dW[2]=in[19]; dBi[2]=in[20]; dW[3]=in[21]; dBi[3]=in[22];
        dg=in[23]; dbb=in[24]; dng=in[25]; dnb=in[26];
        pro_w1=in[27]; pro_b1=in[28]; pro_w2=in[29]; pro_b2=in[30];
    } else {
        pro_w1=in[3]; pro_b1=in[4]; pro_w2=in[5]; pro_b2=in[6];
        eW[0]=in[7];  eW[1]=in[8];  eW[2]=in[9];  eW[3]=in[10];
        eBi[0]=in[11]; eBi[1]=in[12]; eBi[2]=in[13]; eBi[3]=in[14];
        eg=in[15]; ebb=in[16]; eng=in[17]; enb=in[18];
        dW[0]=in[19]; dW[1]=in[20]; dW[2]=in[21]; dW[3]=in[22];
        dBi[0]=in[23]; dBi[1]=in[24]; dBi[2]=in[25]; dBi[3]=in[26];
        dg=in[27]; dbb=in[28]; dng=in[29]; dnb=in[30];
    }

    const float SCALE = 0.044194173824159216f;  // 1/sqrt(512)
    dim3 blk16(16, 16);
    auto gemm = [&](const float* A, const float* B, const float* bias, const float* resid,
                    float* C, int M, int N, int K, long long sA, long long sB, long long sC,
                    int nb, float alpha, int tB, int epi) {
        dim3 grid((N + 63) / 64, (M + 63) / 64, nb);
        gemm_kernel<<<grid, blk16>>>(A, B, bias, resid, C, M, N, K, sA, sB, sC, alpha, tB, epi);
    };

    // ---- embedding + score + selection ----
    pe_kernel<<<TT, 256>>>();
    embed_kernel<<<dim3(TT, BB), 128>>>(x, conv_w, ex);
    score_kernel<<<dim3(TT, BB), 256>>>(ex, score);
    select_kernel<<<BB, TT>>>();
    gather_kernel<<<dim3(TU, BB), 256>>>(ex, xe);

    // ---- encoder (Tc = 512) ----
    {
        int Tc = TU, BT = BB * Tc;
        long long sQK = (long long)Tc * DD, sAtt = (long long)Tc * Tc;
        for (int l = 0; l < LL; l++) {
            const float *Wq = eW[0] + (long long)l * DD * DD, *bq = eBi[0] + l * DD;
            const float *Wk = eW[1] + (long long)l * DD * DD, *bk = eBi[1] + l * DD;
            const float *Wv = eW[2] + (long long)l * DD * DD, *bv = eBi[2] + l * DD;
            const float *Wo = eW[3] + (long long)l * DD * DD, *bo = eBi[3] + l * DD;
            gemm(xe, Wq, bq, nullptr, q, BT, DD, DD, 0, 0, 0, 1, 1.f, 0, 0);
            gemm(xe, Wk, bk, nullptr, k, BT, DD, DD, 0, 0, 0, 1, 1.f, 0, 0);
            gemm(xe, Wv, bv, nullptr, v, BT, DD, DD, 0, 0, 0, 1, 1.f, 0, 0);
            gemm(q, k, nullptr, nullptr, att, Tc, Tc, DD, sQK, sQK, sAtt, BB, SCALE, 1, 0);
            softmax_kernel<<<BB * Tc, 256>>>(att, Tc);
            gemm(att, v, nullptr, nullptr, t1, Tc, DD, Tc, sAtt, sQK, sQK, BB, 1.f, 0, 0);
            add_kernel<<<(int)(((long long)BT * DD + 255) / 256), 256>>>(t1, xe, (long long)BT * DD);
            ln_kernel<<<BT, 256>>>(t1, eg + l * DD, ebb + l * DD, t2);
            gemm(t2, Wo, bo, t1, xe, BT, DD, DD, 0, 0, 0, 1, 1.f, 0, 0);
        }
        ln_kernel<<<BT, 256>>>(xe, eng, enb, t1);       // ux in t1
    }

    // ---- decoder tokens ----
    tokens_kernel<<<dim3(TT, BB), 256>>>(t1, mask_token, tok);

    // ---- decoder (Tc = 1024), attention maps written straight into d_out ----
    {
        int Tc = TT, BT = BB * Tc;
        long long sQK = (long long)Tc * DD, sAtt = (long long)Tc * Tc;
        for (int l = 0; l < LL; l++) {
            const float *Wq = dW[0] + (long long)l * DD * DD, *bq = dBi[0] + l * DD;
            const float *Wk = dW[1] + (long long)l * DD * DD, *bk = dBi[1] + l * DD;
            const float *Wv = dW[2] + (long long)l * DD * DD, *bv = dBi[2] + l * DD;
            const float *Wo = dW[3] + (long long)l * DD * DD, *bo = dBi[3] + l * DD;
            float* attOut = (float*)d_out + (long long)l * BB * TT * TT;
            gemm(tok, Wq, bq, nullptr, q, BT, DD, DD, 0, 0, 0, 1, 1.f, 0, 0);
            gemm(tok, Wk, bk, nullptr, k, BT, DD, DD, 0, 0, 0, 1, 1.f, 0, 0);
            gemm(tok, Wv, bv, nullptr, v, BT, DD, DD, 0, 0, 0, 1, 1.f, 0, 0);
            gemm(q, k, nullptr, nullptr, attOut, Tc, Tc, DD, sQK, sQK, sAtt, BB, SCALE, 1, 0);
            softmax_kernel<<<BB * Tc, 256>>>(attOut, Tc);
            gemm(attOut, v, nullptr, nullptr, t1, Tc, DD, Tc, sAtt, sQK, sQK, BB, 1.f, 0, 0);
            add_kernel<<<(int)(((long long)BT * DD + 255) / 256), 256>>>(t1, tok, (long long)BT * DD);
            ln_kernel<<<BT, 256>>>(t1, dg + l * DD, dbb + l * DD, t2);
            gemm(t2, Wo, bo, t1, tok, BT, DD, DD, 0, 0, 0, 1, 1.f, 0, 0);
        }
        ln_kernel<<<BT, 256>>>(tok, dng, dnb, t1);      // dx in t1

        // ---- projector: rec = sigmoid(gelu(dx@W1+b1)@W2+b2) ----
        float* rec = (float*)d_out + (long long)LL * BB * TT * TT;
        gemm(t1, pro_w1, pro_b1, nullptr, t2, BT, DD, DD, 0, 0, 0, 1, 1.f, 0, 1);
        gemm(t2, pro_w2, pro_b2, nullptr, rec, BT, DD, DD, 0, 0, 0, 1, 1.f, 0, 2);
    }
}

// round 4
// speedup vs baseline: 1.8885x; 1.8885x over previous
#include <cuda_runtime.h>
#include <cuda_bf16.h>
#include <stdint.h>
#include <math.h>

typedef unsigned int u32;

// ---------------- problem constants ----------------
#define BB 8
#define TT 1024
#define CIN 55
#define DD 512
#define LL 3
#define SEQW 10
#define TRR 512          // masked count
#define TU 512           // unmasked count (T - TR)

// ---------------- device scratch ----------------
__device__ float g_pe[TT * DD];
__device__ float g_ex[BB * TT * DD];
__device__ float g_xe[BB * TU * DD];
__device__ float g_q [BB * TT * DD];
__device__ float g_k [BB * TT * DD];
__device__ float g_v [BB * TT * DD];
__device__ float g_att[BB * TU * TU];     // encoder attention scratch
__device__ float g_t1[BB * TT * DD];
__device__ float g_t2[BB * TT * DD];
__device__ float g_tok[BB * TT * DD];
__device__ float g_score[BB * TT];
__device__ int   g_flag[BB * TT];
__device__ int   g_upos[BB * TT];
__device__ int   g_ulist[BB * TU];

// ---------------- PE ----------------
__global__ void pe_kernel() {
    int t = blockIdx.x;
    int i = threadIdx.x;                 // 0..255
    float divv = expf((float)(2 * i) * (-9.210340371976184f / (float)DD));
    float ang = (float)t * divv;
    g_pe[t * DD + 2 * i]     = sinf(ang);
    g_pe[t * DD + 2 * i + 1] = cosf(ang);
}

// ---------------- embedding: circular conv1d + PE ----------------
__global__ void embed_kernel(const float* __restrict__ x, const float* __restrict__ cw,
                             float* __restrict__ ex) {
    int t = blockIdx.x, b = blockIdx.y;
    __shared__ float sw[CIN * 3];
    int tid = threadIdx.x;               // 128 threads
    for (int i = tid; i < CIN * 3; i += 128) {
        int c = i / 3, k = i % 3;
        int tt = t + k - 1;
        if (tt < 0) tt += TT;
        if (tt >= TT) tt -= TT;
        sw[i] = x[((long long)b * TT + tt) * CIN + c];
    }
    __syncthreads();
#pragma unroll
    for (int p = 0; p < 4; p++) {
        int d = tid + p * 128;
        const float* w = cw + (long long)d * (CIN * 3);
        float acc = 0.f;
#pragma unroll 15
        for (int i = 0; i < CIN * 3; i++) acc = fmaf(sw[i], w[i], acc);
        ex[((long long)b * TT + t) * DD + d] = acc + g_pe[t * DD + d];
    }
}

// ---------------- windowed mean/var score ----------------
__global__ void score_kernel(const float* __restrict__ ex, float* __restrict__ score) {
    int t = blockIdx.x, b = blockIdx.y;
    int lo = t - (SEQW - 1); if (lo < 0) lo = 0;
    float inv = 1.f / (float)(t + 1 - lo);
    int tid = threadIdx.x;               // 256
    float vs = 0.f, ms = 0.f;
#pragma unroll
    for (int p = 0; p < 2; p++) {
        int d = tid + p * 256;
        float s1 = 0.f, s2 = 0.f;
        for (int w = lo; w <= t; w++) {
            float v = ex[((long long)b * TT + w) * DD + d];
            s1 += v; s2 += v * v;
        }
        float m = s1 * inv, m2 = s2 * inv;
        vs += m2 - m * m;
        ms += m;
    }
    __shared__ float rv[256], rm[256];
    rv[tid] = vs; rm[tid] = ms; __syncthreads();
    for (int s = 128; s > 0; s >>= 1) {
        if (tid < s) { rv[tid] += rv[tid + s]; rm[tid] += rm[tid + s]; }
        __syncthreads();
    }
    if (tid == 0) score[b * TT + t] = rv[0] / rm[0];
}

// ---------------- selection: rank with top_k tie-break ----------------
__global__ void select_kernel() {
    int b = blockIdx.x;
    int t = threadIdx.x;                 // 1024 threads
    __shared__ float ss[TT];
    __shared__ int   sf[TT];
    float myv = g_score[b * TT + t];
    ss[t] = myv;
    __syncthreads();
    int rank = 0;
    for (int i = 0; i < TT; i++) {
        float o = ss[i];
        rank += (o > myv) || (o == myv && i < t);
    }
    int masked = (rank < TRR) ? 1 : 0;
    sf[t] = masked;
    __syncthreads();
    int ucnt = 0;
    for (int i = 0; i < t; i++) ucnt += (sf[i] == 0);
    g_flag[b * TT + t] = masked;
    if (!masked) {
        g_upos[b * TT + t] = ucnt;
        g_ulist[b * TU + ucnt] = t;
    } else {
        g_upos[b * TT + t] = -1;
    }
}

// ---------------- gather unmasked tokens ----------------
__global__ void gather_kernel(const float* __restrict__ ex, float* __restrict__ xe) {
    int p = blockIdx.x, b = blockIdx.y;
    int t = g_ulist[b * TU + p];
    const float* src = ex + ((long long)b * TT + t) * DD;
    float* dst = xe + ((long long)b * TU + p) * DD;
    for (int d = threadIdx.x; d < DD; d += 256) dst[d] = src[d];
}

// ---------------- build decoder tokens ----------------
__global__ void tokens_kernel(const float* __restrict__ ux, const float* __restrict__ mtk,
                              float* __restrict__ tok) {
    int t = blockIdx.x, b = blockIdx.y;
    float* dst = tok + ((long long)b * TT + t) * DD;
    if (g_flag[b * TT + t]) {
        for (int d = threadIdx.x; d < 512; d += 256)
            dst[d] = mtk[d] + g_pe[t * DD + d];
    } else {
        int p = g_upos[b * TT + t];
        const float* src = ux + ((long long)b * TU + p) * DD;
        for (int d = threadIdx.x; d < 512; d += 256) dst[d] = src[d];
    }
}

// ================= tensor-core split-bf16 GEMM =================
// C[b] = epi(alpha * A[b] @ op(B[b]) + bias + resid[b])
// op(B) = B ([K,N]) if !transB else B^T with B stored [N,K].
// Requires: M % 128 == 0, N % 128 == 0, K % 32 == 0 (true for all call sites).
// Split-bf16: x = hi + lo; A@B ~= Ah@Bh + Ah@Bl + Al@Bh  (err ~2^-16).

#define SA 20   // A smem row stride in 32-bit words (16 data + 4 pad)
#define SB 21   // B smem row stride in 32-bit words (16 data + 5 pad)

__device__ __forceinline__ void split2(float x0, float x1, u32& hi, u32& lo) {
    __nv_bfloat16 h0 = __float2bfloat16(x0);
    __nv_bfloat16 h1 = __float2bfloat16(x1);
    float r0 = x0 - __bfloat162float(h0);
    float r1 = x1 - __bfloat162float(h1);
    __nv_bfloat162 H  = __halves2bfloat162(h0, h1);
    __nv_bfloat162 Lo = __floats2bfloat162_rn(r0, r1);
    hi = *reinterpret_cast<u32*>(&H);
    lo = *reinterpret_cast<u32*>(&Lo);
}

__device__ __forceinline__ void mma16816(float* d, const u32* a, u32 b0, u32 b1) {
    asm volatile(
        "mma.sync.aligned.m16n8k16.row.col.f32.bf16.bf16.f32 "
        "{%0,%1,%2,%3}, {%4,%5,%6,%7}, {%8,%9}, {%0,%1,%2,%3};\n"
        : "+f"(d[0]), "+f"(d[1]), "+f"(d[2]), "+f"(d[3])
        : "r"(a[0]), "r"(a[1]), "r"(a[2]), "r"(a[3]), "r"(b0), "r"(b1));
}

__global__ __launch_bounds__(256)
void tgemm_kernel(const float* __restrict__ A, const float* __restrict__ B,
                  const float* __restrict__ bias, const float* __restrict__ resid,
                  float* __restrict__ C,
                  int M, int N, int K,
                  long long sA, long long sB, long long sC,
                  float alpha, int transB, int epi) {
    __shared__ u32 AsH[128 * SA];
    __shared__ u32 AsL[128 * SA];
    __shared__ u32 BsH[128 * SB];
    __shared__ u32 BsL[128 * SB];

    int bz = blockIdx.z;
    A += (long long)bz * sA;
    B += (long long)bz * sB;
    C += (long long)bz * sC;
    const float* R = resid ? resid + (long long)bz * sC : nullptr;

    int m0 = blockIdx.y * 128;
    int n0 = blockIdx.x * 128;
    int tid = threadIdx.x;
    int lane = tid & 31, wid = tid >> 5;
    int wm = (wid & 1) * 64;          // warp m offset
    int wn = (wid >> 1) * 32;         // warp n offset
    int g = lane >> 2, t4 = lane & 3;

    float acc[4][4][4];
#pragma unroll
    for (int i = 0; i < 4; i++)
#pragma unroll
        for (int j = 0; j < 4; j++)
#pragma unroll
            for (int q = 0; q < 4; q++) acc[i][j][q] = 0.f;

    const float* Ag = A + (long long)m0 * K;

    for (int k0 = 0; k0 < K; k0 += 32) {
        // ---- stage A tile [128 x 32] as hi/lo bf16 pairs ----
#pragma unroll
        for (int p = 0; p < 4; p++) {
            int r = p * 32 + (tid >> 3);
            int c = (tid & 7) * 4;
            float4 v = *(const float4*)(Ag + (long long)r * K + k0 + c);
            u32 h0, l0, h1, l1;
            split2(v.x, v.y, h0, l0);
            split2(v.z, v.w, h1, l1);
            int w = r * SA + (c >> 1);
            AsH[w] = h0; AsH[w + 1] = h1;
            AsL[w] = l0; AsL[w + 1] = l1;
        }
        // ---- stage B tile -> Bs[n][k] hi/lo ----
        if (transB) {
            const float* Bg = B + (long long)n0 * K;
#pragma unroll
            for (int p = 0; p < 4; p++) {
                int r = p * 32 + (tid >> 3);
                int c = (tid & 7) * 4;
                float4 v = *(const float4*)(Bg + (long long)r * K + k0 + c);
                u32 h0, l0, h1, l1;
                split2(v.x, v.y, h0, l0);
                split2(v.z, v.w, h1, l1);
                int w = r * SB + (c >> 1);
                BsH[w] = h0; BsH[w + 1] = h1;
                BsL[w] = l0; BsL[w + 1] = l1;
            }
        } else {
            __nv_bfloat16* bh = (__nv_bfloat16*)BsH;
            __nv_bfloat16* bl = (__nv_bfloat16*)BsL;
            const float* Bg = B + (long long)k0 * N + n0;
            int n = tid & 127;
            int khalf = tid >> 7;  // 0 or 1
#pragma unroll
            for (int p = 0; p < 16; p++) {
                int kk = p * 2 + khalf;
                float v = Bg[(long long)kk * N + n];
                __nv_bfloat16 h = __float2bfloat16(v);
                float rr = v - __bfloat162float(h);
                bh[n * (2 * SB) + kk] = h;
                bl[n * (2 * SB) + kk] = __float2bfloat16(rr);
            }
        }
        __syncthreads();

        // ---- compute: 2 k16 steps ----
#pragma unroll
        for (int kq = 0; kq < 2; kq++) {
            u32 ah[4][4], al[4][4];
#pragma unroll
            for (int mf = 0; mf < 4; mf++) {
                int base = (wm + mf * 16 + g) * SA + kq * 8 + t4;
                ah[mf][0] = AsH[base];
                ah[mf][1] = AsH[base + 8 * SA];
                ah[mf][2] = AsH[base + 4];
                ah[mf][3] = AsH[base + 8 * SA + 4];
                al[mf][0] = AsL[base];
                al[mf][1] = AsL[base + 8 * SA];
                al[mf][2] = AsL[base + 4];
                al[mf][3] = AsL[base + 8 * SA + 4];
            }
#pragma unroll
            for (int nf = 0; nf < 4; nf++) {
                int bbase = (wn + nf * 8 + g) * SB + kq * 8 + t4;
                u32 bh0 = BsH[bbase], bh1 = BsH[bbase + 4];
                u32 bl0 = BsL[bbase], bl1 = BsL[bbase + 4];
#pragma unroll
                for (int mf = 0; mf < 4; mf++) {
                    mma16816(acc[mf][nf], ah[mf], bh0, bh1);
                    mma16816(acc[mf][nf], ah[mf], bl0, bl1);
                    mma16816(acc[mf][nf], al[mf], bh0, bh1);
                }
            }
        }
        __syncthreads();
    }

    // ---- epilogue ----
#pragma unroll
    for (int mf = 0; mf < 4; mf++) {
        int r0 = m0 + wm + mf * 16 + g;
#pragma unroll
        for (int nf = 0; nf < 4; nf++) {
            int cc = n0 + wn + nf * 8 + t4 * 2;
#pragma unroll
            for (int half = 0; half < 2; half++) {
                int r = r0 + half * 8;
                float v0 = acc[mf][nf][half * 2 + 0] * alpha;
                float v1 = acc[mf][nf][half * 2 + 1] * alpha;
                if (bias) { v0 += bias[cc]; v1 += bias[cc + 1]; }
                if (R) {
                    v0 += R[(long long)r * N + cc];
                    v1 += R[(long long)r * N + cc + 1];
                }
                if (epi == 1) {
                    v0 = 0.5f * v0 * (1.f + erff(v0 * 0.7071067811865475f));
                    v1 = 0.5f * v1 * (1.f + erff(v1 * 0.7071067811865475f));
                } else if (epi == 2) {
                    v0 = 1.f / (1.f + __expf(-v0));
                    v1 = 1.f / (1.f + __expf(-v1));
                }
                float2 st = make_float2(v0, v1);
                *(float2*)(C + (long long)r * N + cc) = st;
            }
        }
    }
}

// ---------------- softmax over rows ----------------
__global__ void softmax_kernel(float* __restrict__ S, int Nc) {
    long long row = blockIdx.x;
    float* p = S + row * Nc;
    __shared__ float red[256];
    int tid = threadIdx.x;
    float mx = -1e30f;
    for (int i = tid; i < Nc; i += 256) mx = fmaxf(mx, p[i]);
    red[tid] = mx; __syncthreads();
    for (int s = 128; s > 0; s >>= 1) { if (tid < s) red[tid] = fmaxf(red[tid], red[tid + s]); __syncthreads(); }
    mx = red[0]; __syncthreads();
    float sum = 0.f;
    for (int i = tid; i < Nc; i += 256) { float e = __expf(p[i] - mx); p[i] = e; sum += e; }
    red[tid] = sum; __syncthreads();
    for (int s = 128; s > 0; s >>= 1) { if (tid < s) red[tid] += red[tid + s]; __syncthreads(); }
    float inv = 1.f / red[0];
    for (int i = tid; i < Nc; i += 256) p[i] *= inv;
}

// ---------------- layer norm (row length 512) ----------------
__global__ void ln_kernel(const float* __restrict__ X, const float* __restrict__ g,
                          const float* __restrict__ b, float* __restrict__ Y) {
    long long row = blockIdx.x;
    const float* x = X + row * DD;
    float* y = Y + row * DD;
    __shared__ float red[256];
    int tid = threadIdx.x;
    float v0 = x[tid], v1 = x[tid + 256];
    red[tid] = v0 + v1; __syncthreads();
    for (int s = 128; s > 0; s >>= 1) { if (tid < s) red[tid] += red[tid + s]; __syncthreads(); }
    float mu = red[0] * (1.f / (float)DD); __syncthreads();
    float d0 = v0 - mu, d1 = v1 - mu;
    red[tid] = d0 * d0 + d1 * d1; __syncthreads();
    for (int s = 128; s > 0; s >>= 1) { if (tid < s) red[tid] += red[tid + s]; __syncthreads(); }
    float inv = rsqrtf(red[0] * (1.f / (float)DD) + 1e-5f);
    y[tid]       = d0 * inv * g[tid] + b[tid];
    y[tid + 256] = d1 * inv * g[tid + 256] + b[tid + 256];
}

// ---------------- host orchestration ----------------
extern "C" void kernel_launch(void* const* d_in, const int* in_sizes, int n_in,
                              void* d_out, int out_size) {
    float *pe, *ex, *xe, *q, *k, *v, *att, *t1, *t2, *tok, *score;
    cudaGetSymbolAddress((void**)&pe,  g_pe);
    cudaGetSymbolAddress((void**)&ex,  g_ex);
    cudaGetSymbolAddress((void**)&xe,  g_xe);
    cudaGetSymbolAddress((void**)&q,   g_q);
    cudaGetSymbolAddress((void**)&k,   g_k);
    cudaGetSymbolAddress((void**)&v,   g_v);
    cudaGetSymbolAddress((void**)&att, g_att);
    cudaGetSymbolAddress((void**)&t1,  g_t1);
    cudaGetSymbolAddress((void**)&t2,  g_t2);
    cudaGetSymbolAddress((void**)&tok, g_tok);
    cudaGetSymbolAddress((void**)&score, g_score);

    const float* in[31];
    for (int i = 0; i < 31 && i < n_in; i++) in[i] = (const float*)d_in[i];

    const float *x = in[0], *conv_w = in[1], *mask_token = in[2];
    const float *pro_w1, *pro_b1, *pro_w2, *pro_b2;
    const float *eW[4], *eBi[4], *eg, *ebb, *eng, *enb;
    const float *dW[4], *dBi[4], *dg, *dbb, *dng, *dnb;

    bool sig = (in_sizes[3] == LL * DD * DD);
    if (sig) {
        eW[0]=in[3];  eBi[0]=in[4];  eW[1]=in[5];  eBi[1]=in[6];
        eW[2]=in[7];  eBi[2]=in[8];  eW[3]=in[9];  eBi[3]=in[10];
        eg=in[11]; ebb=in[12]; eng=in[13]; enb=in[14];
        dW[0]=in[15]; dBi[0]=in[16]; dW[1]=in[17]; dBi[1]=in[18];
        dW[2]=in[19]; dBi[2]=in[20]; dW[3]=in[21]; dBi[3]=in[22];
        dg=in[23]; dbb=in[24]; dng=in[25]; dnb=in[26];
        pro_w1=in[27]; pro_b1=in[28]; pro_w2=in[29]; pro_b2=in[30];
    } else {
        pro_w1=in[3]; pro_b1=in[4]; pro_w2=in[5]; pro_b2=in[6];
        eW[0]=in[7];  eW[1]=in[8];  eW[2]=in[9];  eW[3]=in[10];
        eBi[0]=in[11]; eBi[1]=in[12]; eBi[2]=in[13]; eBi[3]=in[14];
        eg=in[15]; ebb=in[16]; eng=in[17]; enb=in[18];
        dW[0]=in[19]; dW[1]=in[20]; dW[2]=in[21]; dW[3]=in[22];
        dBi[0]=in[23]; dBi[1]=in[24]; dBi[2]=in[25]; dBi[3]=in[26];
        dg=in[27]; dbb=in[28]; dng=in[29]; dnb=in[30];
    }

    const float SCALE = 0.044194173824159216f;  // 1/sqrt(512)
    auto gemm = [&](const float* A, const float* B, const float* bias, const float* resid,
                    float* C, int M, int N, int K, long long sA, long long sB, long long sC,
                    int nb, float alpha, int tB, int epi) {
        dim3 grid(N / 128, M / 128, nb);
        tgemm_kernel<<<grid, 256>>>(A, B, bias, resid, C, M, N, K, sA, sB, sC, alpha, tB, epi);
    };

    // ---- embedding + score + selection ----
    pe_kernel<<<TT, 256>>>();
    embed_kernel<<<dim3(TT, BB), 128>>>(x, conv_w, ex);
    score_kernel<<<dim3(TT, BB), 256>>>(ex, score);
    select_kernel<<<BB, TT>>>();
    gather_kernel<<<dim3(TU, BB), 256>>>(ex, xe);

    // ---- encoder (Tc = 512) ----
    {
        int Tc = TU, BT = BB * Tc;
        long long sQK = (long long)Tc * DD, sAtt = (long long)Tc * Tc;
        for (int l = 0; l < LL; l++) {
            const float *Wq = eW[0] + (long long)l * DD * DD, *bq = eBi[0] + l * DD;
            const float *Wk = eW[1] + (long long)l * DD * DD, *bk = eBi[1] + l * DD;
            const float *Wv = eW[2] + (long long)l * DD * DD, *bv = eBi[2] + l * DD;
            const float *Wo = eW[3] + (long long)l * DD * DD, *bo = eBi[3] + l * DD;
            gemm(xe, Wq, bq, nullptr, q, BT, DD, DD, 0, 0, 0, 1, 1.f, 0, 0);
            gemm(xe, Wk, bk, nullptr, k, BT, DD, DD, 0, 0, 0, 1, 1.f, 0, 0);
            gemm(xe, Wv, bv, nullptr, v, BT, DD, DD, 0, 0, 0, 1, 1.f, 0, 0);
            gemm(q, k, nullptr, nullptr, att, Tc, Tc, DD, sQK, sQK, sAtt, BB, SCALE, 1, 0);
            softmax_kernel<<<BB * Tc, 256>>>(att, Tc);
            gemm(att, v, nullptr, xe, t1, Tc, DD, Tc, sAtt, sQK, sQK, BB, 1.f, 0, 0);  // +resid fused
            ln_kernel<<<BT, 256>>>(t1, eg + l * DD, ebb + l * DD, t2);
            gemm(t2, Wo, bo, t1, xe, BT, DD, DD, 0, 0, 0, 1, 1.f, 0, 0);
        }
        ln_kernel<<<BT, 256>>>(xe, eng, enb, t1);       // ux in t1
    }

    // ---- decoder tokens ----
    tokens_kernel<<<dim3(TT, BB), 256>>>(t1, mask_token, tok);

    // ---- decoder (Tc = 1024), attention maps written straight into d_out ----
    {
        int Tc = TT, BT = BB * Tc;
        long long sQK = (long long)Tc * DD, sAtt = (long long)Tc * Tc;
        for (int l = 0; l < LL; l++) {
            const float *Wq = dW[0] + (long long)l * DD * DD, *bq = dBi[0] + l * DD;
            const float *Wk = dW[1] + (long long)l * DD * DD, *bk = dBi[1] + l * DD;
            const float *Wv = dW[2] + (long long)l * DD * DD, *bv = dBi[2] + l * DD;
            const float *Wo = dW[3] + (long long)l * DD * DD, *bo = dBi[3] + l * DD;
            float* attOut = (float*)d_out + (long long)l * BB * TT * TT;
            gemm(tok, Wq, bq, nullptr, q, BT, DD, DD, 0, 0, 0, 1, 1.f, 0, 0);
            gemm(tok, Wk, bk, nullptr, k, BT, DD, DD, 0, 0, 0, 1, 1.f, 0, 0);
            gemm(tok, Wv, bv, nullptr, v, BT, DD, DD, 0, 0, 0, 1, 1.f, 0, 0);
            gemm(q, k, nullptr, nullptr, attOut, Tc, Tc, DD, sQK, sQK, sAtt, BB, SCALE, 1, 0);
            softmax_kernel<<<BB * Tc, 256>>>(attOut, Tc);
            gemm(attOut, v, nullptr, tok, t1, Tc, DD, Tc, sAtt, sQK, sQK, BB, 1.f, 0, 0); // +resid fused
            ln_kernel<<<BT, 256>>>(t1, dg + l * DD, dbb + l * DD, t2);
            gemm(t2, Wo, bo, t1, tok, BT, DD, DD, 0, 0, 0, 1, 1.f, 0, 0);
        }
        ln_kernel<<<BT, 256>>>(tok, dng, dnb, t1);      // dx in t1

        // ---- projector: rec = sigmoid(gelu(dx@W1+b1)@W2+b2) ----
        float* rec = (float*)d_out + (long long)LL * BB * TT * TT;
        gemm(t1, pro_w1, pro_b1, nullptr, t2, BT, DD, DD, 0, 0, 0, 1, 1.f, 0, 1);
        gemm(t2, pro_w2, pro_b2, nullptr, rec, BT, DD, DD, 0, 0, 0, 1, 1.f, 0, 2);
    }
}

// round 6
// speedup vs baseline: 2.3767x; 1.2585x over previous
#include <cuda_runtime.h>
#include <cuda_bf16.h>
#include <stdint.h>
#include <math.h>

typedef unsigned int u32;

// ---------------- problem constants ----------------
#define BB 8
#define TT 1024
#define CIN 55
#define DD 512
#define LL 3
#define SEQW 10
#define TRR 512          // masked count
#define TU 512           // unmasked count (T - TR)

// ---------------- device scratch ----------------
__device__ float g_pe[TT * DD];
__device__ float g_ex[BB * TT * DD];
__device__ float g_xe[BB * TU * DD];
__device__ float g_q [BB * TT * DD];
__device__ float g_k [BB * TT * DD];
__device__ float g_v [BB * TT * DD];
__device__ float g_att[BB * TU * TU];     // encoder attention scratch (fp32)
__device__ float g_t1[BB * TT * DD];
__device__ float g_t2[BB * TT * DD];
__device__ float g_tok[BB * TT * DD];
__device__ float g_score[BB * TT];
__device__ int   g_flag[BB * TT];
__device__ int   g_upos[BB * TT];
__device__ int   g_ulist[BB * TU];

// bf16 hi/lo split scratch
__device__ __nv_bfloat16 g_AH[8u*1024*1024];   // A operand (up to 8.4M elems)
__device__ __nv_bfloat16 g_AL[8u*1024*1024];
__device__ __nv_bfloat16 g_BH[8u*1024*512];    // B operand (up to 4.2M elems)
__device__ __nv_bfloat16 g_BL[8u*1024*512];
__device__ __nv_bfloat16 g_WH[512*512];        // transposed weight
__device__ __nv_bfloat16 g_WL[512*512];

// ---------------- PE ----------------
__global__ void pe_kernel() {
    int t = blockIdx.x;
    int i = threadIdx.x;                 // 0..255
    float divv = expf((float)(2 * i) * (-9.210340371976184f / (float)DD));
    float ang = (float)t * divv;
    g_pe[t * DD + 2 * i]     = sinf(ang);
    g_pe[t * DD + 2 * i + 1] = cosf(ang);
}

// ---------------- embedding: circular conv1d + PE ----------------
__global__ void embed_kernel(const float* __restrict__ x, const float* __restrict__ cw,
                             float* __restrict__ ex) {
    int t = blockIdx.x, b = blockIdx.y;
    __shared__ float sw[CIN * 3];
    int tid = threadIdx.x;               // 128 threads
    for (int i = tid; i < CIN * 3; i += 128) {
        int c = i / 3, k = i % 3;
        int tt = t + k - 1;
        if (tt < 0) tt += TT;
        if (tt >= TT) tt -= TT;
        sw[i] = x[((long long)b * TT + tt) * CIN + c];
    }
    __syncthreads();
#pragma unroll
    for (int p = 0; p < 4; p++) {
        int d = tid + p * 128;
        const float* w = cw + (long long)d * (CIN * 3);
        float acc = 0.f;
#pragma unroll 15
        for (int i = 0; i < CIN * 3; i++) acc = fmaf(sw[i], w[i], acc);
        ex[((long long)b * TT + t) * DD + d] = acc + g_pe[t * DD + d];
    }
}

// ---------------- windowed mean/var score ----------------
__global__ void score_kernel(const float* __restrict__ ex, float* __restrict__ score) {
    int t = blockIdx.x, b = blockIdx.y;
    int lo = t - (SEQW - 1); if (lo < 0) lo = 0;
    float inv = 1.f / (float)(t + 1 - lo);
    int tid = threadIdx.x;               // 256
    float vs = 0.f, ms = 0.f;
#pragma unroll
    for (int p = 0; p < 2; p++) {
        int d = tid + p * 256;
        float s1 = 0.f, s2 = 0.f;
        for (int w = lo; w <= t; w++) {
            float v = ex[((long long)b * TT + w) * DD + d];
            s1 += v; s2 += v * v;
        }
        float m = s1 * inv, m2 = s2 * inv;
        vs += m2 - m * m;
        ms += m;
    }
    __shared__ float rv[256], rm[256];
    rv[tid] = vs; rm[tid] = ms; __syncthreads();
    for (int s = 128; s > 0; s >>= 1) {
        if (tid < s) { rv[tid] += rv[tid + s]; rm[tid] += rm[tid + s]; }
        __syncthreads();
    }
    if (tid == 0) score[b * TT + t] = rv[0] / rm[0];
}

// ---------------- selection: rank with top_k tie-break ----------------
__global__ void select_kernel() {
    int b = blockIdx.x;
    int t = threadIdx.x;                 // 1024 threads
    __shared__ float ss[TT];
    __shared__ int   sf[TT];
    float myv = g_score[b * TT + t];
    ss[t] = myv;
    __syncthreads();
    int rank = 0;
    for (int i = 0; i < TT; i++) {
        float o = ss[i];
        rank += (o > myv) || (o == myv && i < t);
    }
    int masked = (rank < TRR) ? 1 : 0;
    sf[t] = masked;
    __syncthreads();
    int ucnt = 0;
    for (int i = 0; i < t; i++) ucnt += (sf[i] == 0);
    g_flag[b * TT + t] = masked;
    if (!masked) {
        g_upos[b * TT + t] = ucnt;
        g_ulist[b * TU + ucnt] = t;
    } else {
        g_upos[b * TT + t] = -1;
    }
}

// ---------------- gather unmasked tokens ----------------
__global__ void gather_kernel(const float* __restrict__ ex, float* __restrict__ xe) {
    int p = blockIdx.x, b = blockIdx.y;
    int t = g_ulist[b * TU + p];
    const float* src = ex + ((long long)b * TT + t) * DD;
    float* dst = xe + ((long long)b * TU + p) * DD;
    for (int d = threadIdx.x; d < DD; d += 256) dst[d] = src[d];
}

// ---------------- build decoder tokens ----------------
__global__ void tokens_kernel(const float* __restrict__ ux, const float* __restrict__ mtk,
                              float* __restrict__ tok) {
    int t = blockIdx.x, b = blockIdx.y;
    float* dst = tok + ((long long)b * TT + t) * DD;
    if (g_flag[b * TT + t]) {
        for (int d = threadIdx.x; d < 512; d += 256)
            dst[d] = mtk[d] + g_pe[t * DD + d];
    } else {
        int p = g_upos[b * TT + t];
        const float* src = ux + ((long long)b * TU + p) * DD;
        for (int d = threadIdx.x; d < 512; d += 256) dst[d] = src[d];
    }
}

// ================= split / transpose-split prep kernels =================
__global__ void split_kernel(const float* __restrict__ X, __nv_bfloat16* __restrict__ H,
                             __nv_bfloat16* __restrict__ L, int n4) {
    int i = blockIdx.x * blockDim.x + threadIdx.x;
    if (i >= n4) return;
    float4 v = ((const float4*)X)[i];
    __nv_bfloat16 h0 = __float2bfloat16(v.x), h1 = __float2bfloat16(v.y);
    __nv_bfloat16 h2 = __float2bfloat16(v.z), h3 = __float2bfloat16(v.w);
    float r0 = v.x - __bfloat162float(h0), r1 = v.y - __bfloat162float(h1);
    float r2 = v.z - __bfloat162float(h2), r3 = v.w - __bfloat162float(h3);
    __nv_bfloat162* Hp = (__nv_bfloat162*)H;
    __nv_bfloat162* Lp = (__nv_bfloat162*)L;
    Hp[2*i]   = __halves2bfloat162(h0, h1);
    Hp[2*i+1] = __halves2bfloat162(h2, h3);
    Lp[2*i]   = __floats2bfloat162_rn(r0, r1);
    Lp[2*i+1] = __floats2bfloat162_rn(r2, r3);
}

// X: [b][R][C] fp32 -> H,L: [b][C][R] bf16   (R,C multiples of 32)
__global__ void tsplit_kernel(const float* __restrict__ X, __nv_bfloat16* __restrict__ H,
                              __nv_bfloat16* __restrict__ L, int R, int C) {
    __shared__ float tile[32][33];
    int b = blockIdx.z;
    int c0 = blockIdx.x * 32, r0 = blockIdx.y * 32;
    const float* Xb = X + (long long)b * R * C;
    int tx = threadIdx.x, ty = threadIdx.y;   // 32 x 8
#pragma unroll
    for (int i = ty; i < 32; i += 8)
        tile[i][tx] = Xb[(long long)(r0 + i) * C + c0 + tx];
    __syncthreads();
    long long ob = (long long)b * C * R;
#pragma unroll
    for (int i = ty; i < 32; i += 8) {
        float v = tile[tx][i];                // element (r0+tx, c0+i)
        __nv_bfloat16 h = __float2bfloat16(v);
        float rr = v - __bfloat162float(h);
        long long o = ob + (long long)(c0 + i) * R + r0 + tx;
        H[o] = h;
        L[o] = __float2bfloat16(rr);
    }
}

// ================= tensor-core GEMM on pre-split bf16 =================
// C[b] = epi(alpha * A[b] @ B[b]^T + bias + resid[b])
// A: [M,K] row-major (hi/lo), B: [N,K] n-major (hi/lo). M,N %128==0, K%32==0.

#define RSTR 40   // halfwords per smem row (32 data + 8 pad) -> 80B rows, LDSM conflict-free

__device__ __forceinline__ void cpa(u32 dst, const void* src) {
    asm volatile("cp.async.cg.shared.global [%0], [%1], 16;\n" :: "r"(dst), "l"(src));
}
__device__ __forceinline__ void ldsm4(u32* r, u32 addr) {
    asm volatile("ldmatrix.sync.aligned.m8n8.x4.shared.b16 {%0,%1,%2,%3}, [%4];\n"
        : "=r"(r[0]), "=r"(r[1]), "=r"(r[2]), "=r"(r[3]) : "r"(addr));
}
__device__ __forceinline__ void mma16816(float* d, const u32* a, u32 b0, u32 b1) {
    asm volatile(
        "mma.sync.aligned.m16n8k16.row.col.f32.bf16.bf16.f32 "
        "{%0,%1,%2,%3}, {%4,%5,%6,%7}, {%8,%9}, {%0,%1,%2,%3};\n"
        : "+f"(d[0]), "+f"(d[1]), "+f"(d[2]), "+f"(d[3])
        : "r"(a[0]), "r"(a[1]), "r"(a[2]), "r"(a[3]), "r"(b0), "r"(b1));
}

#define PARTB (128 * RSTR * 2)     // bytes per part
#define STAGEB (4 * PARTB)         // bytes per stage

__device__ __forceinline__ void load_stage(
    u32 sbase, const __nv_bfloat16* Ah, const __nv_bfloat16* Al,
    const __nv_bfloat16* Bh, const __nv_bfloat16* Bl,
    int m0, int n0, int K, int k0, int tid) {
    int r = tid >> 2, c = tid & 3;
    u32 off1 = (u32)(r * RSTR + c * 8) * 2;
    u32 off2 = (u32)((r + 64) * RSTR + c * 8) * 2;
    long long a1 = (long long)(m0 + r) * K + k0 + c * 8;
    long long a2 = a1 + (long long)64 * K;
    long long b1 = (long long)(n0 + r) * K + k0 + c * 8;
    long long b2 = b1 + (long long)64 * K;
    cpa(sbase + off1, Ah + a1);               cpa(sbase + off2, Ah + a2);
    cpa(sbase + PARTB + off1, Al + a1);       cpa(sbase + PARTB + off2, Al + a2);
    cpa(sbase + 2*PARTB + off1, Bh + b1);     cpa(sbase + 2*PARTB + off2, Bh + b2);
    cpa(sbase + 3*PARTB + off1, Bl + b1);     cpa(sbase + 3*PARTB + off2, Bl + b2);
    asm volatile("cp.async.commit_group;\n");
}

__global__ __launch_bounds__(256)
void gemm2_kernel(const __nv_bfloat16* __restrict__ Ah, const __nv_bfloat16* __restrict__ Al,
                  const __nv_bfloat16* __restrict__ Bh, const __nv_bfloat16* __restrict__ Bl,
                  const float* __restrict__ bias, const float* __restrict__ resid,
                  float* __restrict__ C, int M, int N, int K,
                  long long sA, long long sB, long long sC,
                  float alpha, int epi) {
    extern __shared__ __nv_bfloat16 smraw[];
    u32 smb = (u32)__cvta_generic_to_shared(smraw);

    int bz = blockIdx.z;
    Ah += (long long)bz * sA; Al += (long long)bz * sA;
    Bh += (long long)bz * sB; Bl += (long long)bz * sB;
    C  += (long long)bz * sC;
    const float* R = resid ? resid + (long long)bz * sC : nullptr;

    int m0 = blockIdx.y * 128, n0 = blockIdx.x * 128;
    int tid = threadIdx.x, lane = tid & 31, wid = tid >> 5;
    int wm = (wid & 1) * 64, wn = (wid >> 1) * 32;
    int g = lane >> 2, t4 = lane & 3;

    float acc[4][4][4];
#pragma unroll
    for (int i = 0; i < 4; i++)
#pragma unroll
        for (int j = 0; j < 4; j++)
#pragma unroll
            for (int q = 0; q < 4; q++) acc[i][j][q] = 0.f;

    int nk = K / 32;
    load_stage(smb, Ah, Al, Bh, Bl, m0, n0, K, 0, tid);
    load_stage(smb + STAGEB, Ah, Al, Bh, Bl, m0, n0, K, 32, tid);

    // ldmatrix lane addressing (precompute)
    int arow = lane & 15;
    int achkbase = lane >> 4;                    // +0/+1 chunk
    int brow = (lane & 7) + ((lane & 16) >> 1);  // rows 0-7 / 8-15
    int bchkbase = (lane >> 3) & 1;

    for (int kt = 0; kt < nk; kt++) {
        asm volatile("cp.async.wait_group 1;\n");
        __syncthreads();
        u32 base = smb + (kt & 1) * STAGEB;
        u32 aH = base, aL = base + PARTB, bH = base + 2*PARTB, bL = base + 3*PARTB;
#pragma unroll
        for (int kq = 0; kq < 2; kq++) {
            u32 ah[4][4], al[4][4];
            int achk = kq * 2 + achkbase;
#pragma unroll
            for (int mf = 0; mf < 4; mf++) {
                u32 off = (u32)((wm + mf * 16 + arow) * RSTR + achk * 8) * 2;
                ldsm4(ah[mf], aH + off);
                ldsm4(al[mf], aL + off);
            }
            int bchk = kq * 2 + bchkbase;
#pragma unroll
            for (int np = 0; np < 2; np++) {
                u32 off = (u32)((wn + np * 16 + brow) * RSTR + bchk * 8) * 2;
                u32 bh[4], bl[4];
                ldsm4(bh, bH + off);
                ldsm4(bl, bL + off);
#pragma unroll
                for (int ni = 0; ni < 2; ni++) {
                    int nf = np * 2 + ni;
                    u32 b0h = bh[ni*2], b1h = bh[ni*2+1];
                    u32 b0l = bl[ni*2], b1l = bl[ni*2+1];
#pragma unroll
                    for (int mf = 0; mf < 4; mf++) {
                        mma16816(acc[mf][nf], ah[mf], b0h, b1h);
                        mma16816(acc[mf][nf], ah[mf], b0l, b1l);
                        mma16816(acc[mf][nf], al[mf], b0h, b1h);
                    }
                }
            }
        }
        __syncthreads();
        if (kt + 2 < nk)
            load_stage(smb + (kt & 1) * STAGEB, Ah, Al, Bh, Bl, m0, n0, K, (kt + 2) * 32, tid);
        else
            asm volatile("cp.async.commit_group;\n");
    }

    // ---- epilogue ----
#pragma unroll
    for (int mf = 0; mf < 4; mf++) {
        int r0 = m0 + wm + mf * 16 + g;
#pragma unroll
        for (int nf = 0; nf < 4; nf++) {
            int cc = n0 + wn + nf * 8 + t4 * 2;
#pragma unroll
            for (int half = 0; half < 2; half++) {
                int r = r0 + half * 8;
                float v0 = acc[mf][nf][half * 2 + 0] * alpha;
                float v1 = acc[mf][nf][half * 2 + 1] * alpha;
                if (bias) { v0 += bias[cc]; v1 += bias[cc + 1]; }
                if (R) {
                    v0 += R[(long long)r * N + cc];
                    v1 += R[(long long)r * N + cc + 1];
                }
                if (epi == 1) {
                    v0 = 0.5f * v0 * (1.f + erff(v0 * 0.7071067811865475f));
                    v1 = 0.5f * v1 * (1.f + erff(v1 * 0.7071067811865475f));
                } else if (epi == 2) {
                    v0 = 1.f / (1.f + __expf(-v0));
                    v1 = 1.f / (1.f + __expf(-v1));
                }
                *(float2*)(C + (long long)r * N + cc) = make_float2(v0, v1);
            }
        }
    }
}

// ---------------- softmax over rows ----------------
__global__ void softmax_kernel(float* __restrict__ S, int Nc) {
    long long row = blockIdx.x;
    float* p = S + row * Nc;
    __shared__ float red[256];
    int tid = threadIdx.x;
    float mx = -1e30f;
    for (int i = tid; i < Nc; i += 256) mx = fmaxf(mx, p[i]);
    red[tid] = mx; __syncthreads();
    for (int s = 128; s > 0; s >>= 1) { if (tid < s) red[tid] = fmaxf(red[tid], red[tid + s]); __syncthreads(); }
    mx = red[0]; __syncthreads();
    float sum = 0.f;
    for (int i = tid; i < Nc; i += 256) { float e = __expf(p[i] - mx); p[i] = e; sum += e; }
    red[tid] = sum; __syncthreads();
    for (int s = 128; s > 0; s >>= 1) { if (tid < s) red[tid] += red[tid + s]; __syncthreads(); }
    float inv = 1.f / red[0];
    for (int i = tid; i < Nc; i += 256) p[i] *= inv;
}

// ---------------- layer norm (row length 512) ----------------
__global__ void ln_kernel(const float* __restrict__ X, const float* __restrict__ g,
                          const float* __restrict__ b, float* __restrict__ Y) {
    long long row = blockIdx.x;
    const float* x = X + row * DD;
    float* y = Y + row * DD;
    __shared__ float red[256];
    int tid = threadIdx.x;
    float v0 = x[tid], v1 = x[tid + 256];
    red[tid] = v0 + v1; __syncthreads();
    for (int s = 128; s > 0; s >>= 1) { if (tid < s) red[tid] += red[tid + s]; __syncthreads(); }
    float mu = red[0] * (1.f / (float)DD); __syncthreads();
    float d0 = v0 - mu, d1 = v1 - mu;
    red[tid] = d0 * d0 + d1 * d1; __syncthreads();
    for (int s = 128; s > 0; s >>= 1) { if (tid < s) red[tid] += red[tid + s]; __syncthreads(); }
    float inv = rsqrtf(red[0] * (1.f / (float)DD) + 1e-5f);
    y[tid]       = d0 * inv * g[tid] + b[tid];
    y[tid + 256] = d1 * inv * g[tid + 256] + b[tid + 256];
}

// ---------------- host orchestration ----------------
extern "C" void kernel_launch(void* const* d_in, const int* in_sizes, int n_in,
                              void* d_out, int out_size) {
    float *ex, *xe, *q, *k, *v, *att, *t1, *t2, *tok, *score;
    cudaGetSymbolAddress((void**)&ex,  g_ex);
    cudaGetSymbolAddress((void**)&xe,  g_xe);
    cudaGetSymbolAddress((void**)&q,   g_q);
    cudaGetSymbolAddress((void**)&k,   g_k);
    cudaGetSymbolAddress((void**)&v,   g_v);
    cudaGetSymbolAddress((void**)&att, g_att);
    cudaGetSymbolAddress((void**)&t1,  g_t1);
    cudaGetSymbolAddress((void**)&t2,  g_t2);
    cudaGetSymbolAddress((void**)&tok, g_tok);
    cudaGetSymbolAddress((void**)&score, g_score);
    __nv_bfloat16 *AH, *AL, *BH, *BL, *WH, *WL;
    cudaGetSymbolAddress((void**)&AH, g_AH);
    cudaGetSymbolAddress((void**)&AL, g_AL);
    cudaGetSymbolAddress((void**)&BH, g_BH);
    cudaGetSymbolAddress((void**)&BL, g_BL);
    cudaGetSymbolAddress((void**)&WH, g_WH);
    cudaGetSymbolAddress((void**)&WL, g_WL);

    static int smem_set = 0;
    if (!smem_set) {
        cudaFuncSetAttribute(gemm2_kernel, cudaFuncAttributeMaxDynamicSharedMemorySize, 2 * STAGEB);
        smem_set = 1;
    }

    const float* in[31];
    for (int i = 0; i < 31 && i < n_in; i++) in[i] = (const float*)d_in[i];

    const float *x = in[0], *conv_w = in[1], *mask_token = in[2];
    const float *pro_w1, *pro_b1, *pro_w2, *pro_b2;
    const float *eW[4], *eBi[4], *eg, *ebb, *eng, *enb;
    const float *dW[4], *dBi[4], *dg, *dbb, *dng, *dnb;

    bool sig = (in_sizes[3] == LL * DD * DD);
    if (sig) {
        eW[0]=in[3];  eBi[0]=in[4];  eW[1]=in[5];  eBi[1]=in[6];
        eW[2]=in[7];  eBi[2]=in[8];  eW[3]=in[9];  eBi[3]=in[10];
        eg=in[11]; ebb=in[12]; eng=in[13]; enb=in[14];
        dW[0]=in[15]; dBi[0]=in[16]; dW[1]=in[17]; dBi[1]=in[18];
        dW[2]=in[19]; dBi[2]=in[20]; dW[3]=in[21]; dBi[3]=in[22];
        dg=in[23]; dbb=in[24]; dng=in[25]; dnb=in[26];
        pro_w1=in[27]; pro_b1=in[28]; pro_w2=in[29]; pro_b2=in[30];
    } else {
        pro_w1=in[3]; pro_b1=in[4]; pro_w2=in[5]; pro_b2=in[6];
        eW[0]=in[7];  eW[1]=in[8];  eW[2]=in[9];  eW[3]=in[10];
        eBi[0]=in[11]; eBi[1]=in[12]; eBi[2]=in[13]; eBi[3]=in[14];
        eg=in[15]; ebb=in[16]; eng=in[17]; enb=in[18];
        dW[0]=in[19]; dW[1]=in[20]; dW[2]=in[21]; dW[3]=in[22];
        dBi[0]=in[23]; dBi[1]=in[24]; dBi[2]=in[25]; dBi[3]=in[26];
        dg=in[27]; dbb=in[28]; dng=in[29]; dnb=in[30];
    }

    const float SCALE = 0.044194173824159216f;  // 1/sqrt(512)

    auto split = [&](const float* X, __nv_bfloat16* H, __nv_bfloat16* L, long long n) {
        int n4 = (int)(n / 4);
        split_kernel<<<(n4 + 255) / 256, 256>>>(X, H, L, n4);
    };
    auto tsplit = [&](const float* X, __nv_bfloat16* H, __nv_bfloat16* L, int R, int C, int nb) {
        tsplit_kernel<<<dim3(C / 32, R / 32, nb), dim3(32, 8)>>>(X, H, L, R, C);
    };
    auto gemm = [&](const __nv_bfloat16* ah, const __nv_bfloat16* al,
                    const __nv_bfloat16* bh, const __nv_bfloat16* bl,
                    const float* bias, const float* resid, float* C,
                    int M, int N, int K, long long sA, long long sB, long long sC,
                    int nb, float alpha, int epi) {
        dim3 grid(N / 128, M / 128, nb);
        gemm2_kernel<<<grid, 256, 2 * STAGEB>>>(ah, al, bh, bl, bias, resid, C,
                                                M, N, K, sA, sB, sC, alpha, epi);
    };
    auto wprep = [&](const float* W) { tsplit(W, WH, WL, DD, DD, 1); };

    // ---- embedding + score + selection ----
    pe_kernel<<<TT, 256>>>();
    embed_kernel<<<dim3(TT, BB), 128>>>(x, conv_w, ex);
    score_kernel<<<dim3(TT, BB), 256>>>(ex, score);
    select_kernel<<<BB, TT>>>();
    gather_kernel<<<dim3(TU, BB), 256>>>(ex, xe);

    // ---- encoder (Tc = 512) ----
    {
        int Tc = TU, BT = BB * Tc;
        long long sQK = (long long)Tc * DD, sAtt = (long long)Tc * Tc;
        for (int l = 0; l < LL; l++) {
            const float *Wq = eW[0] + (long long)l * DD * DD, *bq = eBi[0] + l * DD;
            const float *Wk = eW[1] + (long long)l * DD * DD, *bk = eBi[1] + l * DD;
            const float *Wv = eW[2] + (long long)l * DD * DD, *bv = eBi[2] + l * DD;
            const float *Wo = eW[3] + (long long)l * DD * DD, *bo = eBi[3] + l * DD;
            split(xe, AH, AL, (long long)BT * DD);
            wprep(Wq); gemm(AH, AL, WH, WL, bq, nullptr, q, BT, DD, DD, 0, 0, 0, 1, 1.f, 0);
            wprep(Wk); gemm(AH, AL, WH, WL, bk, nullptr, k, BT, DD, DD, 0, 0, 0, 1, 1.f, 0);
            wprep(Wv); gemm(AH, AL, WH, WL, bv, nullptr, v, BT, DD, DD, 0, 0, 0, 1, 1.f, 0);
            split(q, AH, AL, (long long)BT * DD);
            split(k, BH, BL, (long long)BT * DD);
            gemm(AH, AL, BH, BL, nullptr, nullptr, att, Tc, Tc, DD, sQK, sQK, sAtt, BB, SCALE, 0);
            softmax_kernel<<<BB * Tc, 256>>>(att, Tc);
            split(att, AH, AL, (long long)BB * Tc * Tc);
            tsplit(v, BH, BL, Tc, DD, BB);           // [b][D][Tc]
            gemm(AH, AL, BH, BL, nullptr, xe, t1, Tc, DD, Tc, sAtt, sQK, sQK, BB, 1.f, 0);
            ln_kernel<<<BT, 256>>>(t1, eg + l * DD, ebb + l * DD, t2);
            split(t2, AH, AL, (long long)BT * DD);
            wprep(Wo); gemm(AH, AL, WH, WL, bo, t1, xe, BT, DD, DD, 0, 0, 0, 1, 1.f, 0);
        }
        ln_kernel<<<BT, 256>>>(xe, eng, enb, t1);    // ux in t1
    }

    // ---- decoder tokens ----
    tokens_kernel<<<dim3(TT, BB), 256>>>(t1, mask_token, tok);

    // ---- decoder (Tc = 1024), attention maps into d_out ----
    {
        int Tc = TT, BT = BB * Tc;
        long long sQK = (long long)Tc * DD, sAtt = (long long)Tc * Tc;
        for (int l = 0; l < LL; l++) {
            const float *Wq = dW[0] + (long long)l * DD * DD, *bq = dBi[0] + l * DD;
            const float *Wk = dW[1] + (long long)l * DD * DD, *bk = dBi[1] + l * DD;
            const float *Wv = dW[2] + (long long)l * DD * DD, *bv = dBi[2] + l * DD;
            const float *Wo = dW[3] + (long long)l * DD * DD, *bo = dBi[3] + l * DD;
            float* attOut = (float*)d_out + (long long)l * BB * TT * TT;
            split(tok, AH, AL, (long long)BT * DD);
            wprep(Wq); gemm(AH, AL, WH, WL, bq, nullptr, q, BT, DD, DD, 0, 0, 0, 1, 1.f, 0);
            wprep(Wk); gemm(AH, AL, WH, WL, bk, nullptr, k, BT, DD, DD, 0, 0, 0, 1, 1.f, 0);
            wprep(Wv); gemm(AH, AL, WH, WL, bv, nullptr, v, BT, DD, DD, 0, 0, 0, 1, 1.f, 0);
            split(q, AH, AL, (long long)BT * DD);
            split(k, BH, BL, (long long)BT * DD);
            gemm(AH, AL, BH, BL, nullptr, nullptr, attOut, Tc, Tc, DD, sQK, sQK, sAtt, BB, SCALE, 0);
            softmax_kernel<<<BB * Tc, 256>>>(attOut, Tc);
            split(attOut, AH, AL, (long long)BB * Tc * Tc);
            tsplit(v, BH, BL, Tc, DD, BB);           // [b][D][Tc]
            gemm(AH, AL, BH, BL, nullptr, tok, t1, Tc, DD, Tc, sAtt, sQK, sQK, BB, 1.f, 0);
            ln_kernel<<<BT, 256>>>(t1, dg + l * DD, dbb + l * DD, t2);
            split(t2, AH, AL, (long long)BT * DD);
            wprep(Wo); gemm(AH, AL, WH, WL, bo, t1, tok, BT, DD, DD, 0, 0, 0, 1, 1.f, 0);
        }
        ln_kernel<<<BT, 256>>>(tok, dng, dnb, t1);   // dx in t1

        // ---- projector: rec = sigmoid(gelu(dx@W1+b1)@W2+b2) ----
        float* rec = (float*)d_out + (long long)LL * BB * TT * TT;
        split(t1, AH, AL, (long long)BT * DD);
        wprep(pro_w1); gemm(AH, AL, WH, WL, pro_b1, nullptr, t2, BT, DD, DD, 0, 0, 0, 1, 1.f, 1);
        split(t2, AH, AL, (long long)BT * DD);
        wprep(pro_w2); gemm(AH, AL, WH, WL, pro_b2, nullptr, rec, BT, DD, DD, 0, 0, 0, 1, 1.f, 2);
    }
}